// round 9
// baseline (speedup 1.0000x reference)
#include <cuda_runtime.h>
#include <cstdint>

// IFOPooling: h_t = f_t * h_{t-1} + i_t * z_t over seq (last dim, contiguous).
// [B=16, H=1024, S=2048] fp32 -> 16384 rows of 2048.
//
// R9: cp.async smem-pipelined. 2048 CTAs x 8 rows. Double-buffered smem
// tiles (2 x {f,z,i} x 8KB = 48KB); row i+1's 24KB streams via the async
// copy engine while row i is scanned from smem and stored. DMA keeps reads
// outstanding through the compute tail at zero register cost.

#define SEQ   2048
#define TPB   256
#define EPT   8
#define ROWS  16384
#define GRID  2048
#define RPC   (ROWS / GRID)          // 8
#define STAGE_FLOATS (3 * SEQ)       // f,z,i per stage
#define SMEM_BYTES (2 * STAGE_FLOATS * 4 + 64)

__device__ __forceinline__ uint32_t s2u(const void* p) {
    uint32_t a;
    asm("{ .reg .u64 t; cvta.to.shared.u64 t, %1; cvt.u32.u64 %0, t; }"
        : "=r"(a) : "l"(p));
    return a;
}

__device__ __forceinline__ void cpa16(uint32_t s, const float* g) {
    asm volatile("cp.async.cg.shared.global [%0], [%1], 16;" :: "r"(s), "l"(g));
}

__device__ __forceinline__ void stg256(float* p, const float r[8]) {
    asm volatile(
        "st.global.L1::evict_first.v8.f32 [%0], {%1,%2,%3,%4,%5,%6,%7,%8};"
        :: "l"(p),
           "f"(r[0]), "f"(r[1]), "f"(r[2]), "f"(r[3]),
           "f"(r[4]), "f"(r[5]), "f"(r[6]), "f"(r[7])
        : "memory");
}

__global__ __launch_bounds__(TPB) void ifo_scan_kernel(
    const float* __restrict__ f,
    const float* __restrict__ z,
    const float* __restrict__ ig,
    float* __restrict__ out)
{
    extern __shared__ float smem[];
    float* sFagg = smem + 2 * STAGE_FLOATS;   // 8 floats
    float* sXagg = sFagg + 8;

    const int t = threadIdx.x;
    const unsigned lane = t & 31u;
    const unsigned warp = t >> 5;
    const uint32_t sbase = s2u(smem);
    const int row0 = blockIdx.x;

    // ---- issue one row's 3 tiles into a stage (6 x 16B cp.async / thread) ----
    auto issue = [&](int stage, int row) {
        const uint32_t dst = sbase + (uint32_t)stage * (STAGE_FLOATS * 4);
        const int goff = row * SEQ;
        const float* gf = f  + goff;
        const float* gz = z  + goff;
        const float* gi = ig + goff;
        cpa16(dst              + t * 16,          gf + t * 4);
        cpa16(dst              + (t + 256) * 16,  gf + (t + 256) * 4);
        cpa16(dst + SEQ * 4    + t * 16,          gz + t * 4);
        cpa16(dst + SEQ * 4    + (t + 256) * 16,  gz + (t + 256) * 4);
        cpa16(dst + 2 * SEQ * 4 + t * 16,         gi + t * 4);
        cpa16(dst + 2 * SEQ * 4 + (t + 256) * 16, gi + (t + 256) * 4);
        asm volatile("cp.async.commit_group;");
    };

    issue(0, row0);

    #pragma unroll
    for (int it = 0; it < RPC; it++) {
        const int row   = row0 + it * GRID;
        const int stage = it & 1;

        if (it + 1 < RPC) {
            issue(stage ^ 1, row + GRID);
            asm volatile("cp.async.wait_group 1;");
        } else {
            asm volatile("cp.async.wait_group 0;");
        }
        __syncthreads();   // stage tiles ready (all threads' copies visible)

        // ---- read this thread's 8 elements of each array from smem ----
        const float* sf = smem + stage * STAGE_FLOATS;
        const float* sz = sf + SEQ;
        const float* si = sz + SEQ;
        float4 fa = *reinterpret_cast<const float4*>(sf + t * EPT);
        float4 fb = *reinterpret_cast<const float4*>(sf + t * EPT + 4);
        float4 za = *reinterpret_cast<const float4*>(sz + t * EPT);
        float4 zb = *reinterpret_cast<const float4*>(sz + t * EPT + 4);
        float4 ia = *reinterpret_cast<const float4*>(si + t * EPT);
        float4 ib = *reinterpret_cast<const float4*>(si + t * EPT + 4);

        float fv[EPT] = {fa.x, fa.y, fa.z, fa.w, fb.x, fb.y, fb.z, fb.w};
        float xv[EPT];
        xv[0] = ia.x * za.x; xv[1] = ia.y * za.y; xv[2] = ia.z * za.z; xv[3] = ia.w * za.w;
        xv[4] = ib.x * zb.x; xv[5] = ib.y * zb.y; xv[6] = ib.z * zb.z; xv[7] = ib.w * zb.w;

        // local segment composite (F, X): h_out = F*h_in + X
        float F = 1.0f, X = 0.0f;
        #pragma unroll
        for (int j = 0; j < EPT; j++) {
            X = fmaf(fv[j], X, xv[j]);
            F *= fv[j];
        }

        // inclusive warp scan of composites
        float Fs = F, Xs = X;
        #pragma unroll
        for (int d = 1; d < 32; d <<= 1) {
            float Fo = __shfl_up_sync(0xFFFFFFFFu, Fs, d);
            float Xo = __shfl_up_sync(0xFFFFFFFFu, Xs, d);
            if (lane >= (unsigned)d) {
                Xs = fmaf(Fs, Xo, Xs);   // (Fo,Xo) then (Fs,Xs)
                Fs = Fs * Fo;
            }
        }

        if (lane == 31) { sFagg[warp] = Fs; sXagg[warp] = Xs; }
        __syncthreads();   // aggregates ready; also releases this stage buffer

        float Xc = 0.0f;
        #pragma unroll
        for (int w = 0; w < TPB / 32; w++) {
            if (w < (int)warp) Xc = fmaf(sFagg[w], Xc, sXagg[w]);
        }

        float Fex = __shfl_up_sync(0xFFFFFFFFu, Fs, 1);
        float Xex = __shfl_up_sync(0xFFFFFFFFu, Xs, 1);
        if (lane == 0) { Fex = 1.0f; Xex = 0.0f; }

        float h = fmaf(Fex, Xc, Xex);

        // replay from registers, one 256-bit store
        float r[EPT];
        #pragma unroll
        for (int j = 0; j < EPT; j++) {
            h = fmaf(fv[j], h, xv[j]);
            r[j] = h;
        }
        stg256(out + row * SEQ + t * EPT, r);
    }
}

extern "C" void kernel_launch(void* const* d_in, const int* in_sizes, int n_in,
                              void* d_out, int out_size)
{
    const float* f  = (const float*)d_in[0];
    const float* z  = (const float*)d_in[1];
    const float* ig = (const float*)d_in[2];
    float* out = (float*)d_out;

    cudaFuncSetAttribute(ifo_scan_kernel,
                         cudaFuncAttributeMaxDynamicSharedMemorySize, SMEM_BYTES);
    ifo_scan_kernel<<<GRID, TPB, SMEM_BYTES>>>(f, z, ig, out);
}

// round 10
// speedup vs baseline: 1.0560x; 1.0560x over previous
#include <cuda_runtime.h>

// IFOPooling: h_t = f_t * h_{t-1} + i_t * z_t over seq (last dim, contiguous).
// [B=16, H=1024, S=2048] fp32 -> 16384 rows of 2048.
//
// R10: R6 structure exactly (TPB=256, EPT=8, 256-bit ld/st, one barrier per
// row), but 2 rows per CTA in a plain sequential loop. No prefetch buffers,
// no extra registers: stores are issue-only, so row 1's load burst issues
// ~50 cycles after row 0's stores, removing the CTA drain/relaunch gap.

#define SEQ  2048
#define TPB  256
#define EPT  8
#define RPC  2                  // rows per CTA
#define ROWS 16384
#define GRID (ROWS / RPC)       // 8192

__device__ __forceinline__ void ldg256(const float* p, float r[8]) {
    asm volatile(
        "ld.global.L1::evict_first.v8.f32 {%0,%1,%2,%3,%4,%5,%6,%7}, [%8];"
        : "=f"(r[0]), "=f"(r[1]), "=f"(r[2]), "=f"(r[3]),
          "=f"(r[4]), "=f"(r[5]), "=f"(r[6]), "=f"(r[7])
        : "l"(p));
}

__device__ __forceinline__ void stg256(float* p, const float r[8]) {
    asm volatile(
        "st.global.L1::evict_first.v8.f32 [%0], {%1,%2,%3,%4,%5,%6,%7,%8};"
        :: "l"(p),
           "f"(r[0]), "f"(r[1]), "f"(r[2]), "f"(r[3]),
           "f"(r[4]), "f"(r[5]), "f"(r[6]), "f"(r[7])
        : "memory");
}

__global__ __launch_bounds__(TPB, 6) void ifo_scan_kernel(
    const float* __restrict__ f,
    const float* __restrict__ z,
    const float* __restrict__ ig,
    float* __restrict__ out)
{
    const int t = threadIdx.x;
    const unsigned lane = t & 31u;
    const unsigned warp = t >> 5;

    __shared__ float sF[2][TPB / 32];
    __shared__ float sX[2][TPB / 32];

    #pragma unroll
    for (int it = 0; it < RPC; it++) {
        const int row = blockIdx.x * RPC + it;
        const int off = row * SEQ + t * EPT;

        // ---- Phase 1: 3 front-batched 256-bit loads ----
        float fv[EPT], zv[EPT], iv[EPT];
        ldg256(f  + off, fv);
        ldg256(z  + off, zv);
        ldg256(ig + off, iv);

        float xv[EPT];
        #pragma unroll
        for (int j = 0; j < EPT; j++) xv[j] = iv[j] * zv[j];

        // local segment composite (F, X): h_out = F*h_in + X
        float F = 1.0f, X = 0.0f;
        #pragma unroll
        for (int j = 0; j < EPT; j++) {
            X = fmaf(fv[j], X, xv[j]);
            F *= fv[j];
        }

        // ---- Phase 2: inclusive warp scan of composites ----
        float Fs = F, Xs = X;
        #pragma unroll
        for (int d = 1; d < 32; d <<= 1) {
            float Fo = __shfl_up_sync(0xFFFFFFFFu, Fs, d);
            float Xo = __shfl_up_sync(0xFFFFFFFFu, Xs, d);
            if (lane >= (unsigned)d) {
                Xs = fmaf(Fs, Xo, Xs);   // (Fo,Xo) then (Fs,Xs)
                Fs = Fs * Fo;
            }
        }

        // warp aggregates -> double-buffered smem slot; one barrier per row
        if (lane == 31) { sF[it][warp] = Fs; sX[it][warp] = Xs; }
        __syncthreads();

        float Xc = 0.0f;
        #pragma unroll
        for (int w = 0; w < TPB / 32; w++) {
            if (w < (int)warp) Xc = fmaf(sF[it][w], Xc, sX[it][w]);
        }

        float Fex = __shfl_up_sync(0xFFFFFFFFu, Fs, 1);
        float Xex = __shfl_up_sync(0xFFFFFFFFu, Xs, 1);
        if (lane == 0) { Fex = 1.0f; Xex = 0.0f; }

        float h = fmaf(Fex, Xc, Xex);

        // ---- Phase 3: replay, one 256-bit store ----
        float r[EPT];
        #pragma unroll
        for (int j = 0; j < EPT; j++) {
            h = fmaf(fv[j], h, xv[j]);
            r[j] = h;
        }
        stg256(out + off, r);
    }
}

extern "C" void kernel_launch(void* const* d_in, const int* in_sizes, int n_in,
                              void* d_out, int out_size)
{
    const float* f  = (const float*)d_in[0];
    const float* z  = (const float*)d_in[1];
    const float* ig = (const float*)d_in[2];
    float* out = (float*)d_out;

    ifo_scan_kernel<<<GRID, TPB>>>(f, z, ig, out);
}

// round 11
// speedup vs baseline: 1.0599x; 1.0037x over previous
#include <cuda_runtime.h>

// IFOPooling: h_t = f_t * h_{t-1} + i_t * z_t over seq (last dim, contiguous).
// [B=16, H=1024, S=2048] fp32 -> 16384 rows of 2048.
//
// FINAL (R6 champion): block-per-row, TPB=256, EPT=8, Blackwell 256-bit
// global loads/stores (ld/st.global.v8.f32 -> LDG.E.256/STG.E.256),
// evict-first policy (zero reuse). Three-phase affine scan:
//   segment composite: h_out = F*h_in + X;  (F1,X1)∘(F2,X2) = (F1F2, F2X1+X2)
// Measured: 73.0 us kernel, 7.02 TB/s (88.6% DRAM), traffic = exact 512.5 MB
// minimum. 10 structural variants all landed 81-89% DRAM; this is the wall.

#define SEQ 2048
#define TPB 256
#define EPT 8   // elements per thread

// 256-bit global load: 8 floats, ptr must be 32B-aligned.
__device__ __forceinline__ void ldg256(const float* p, float r[8]) {
    asm volatile(
        "ld.global.L1::evict_first.v8.f32 {%0,%1,%2,%3,%4,%5,%6,%7}, [%8];"
        : "=f"(r[0]), "=f"(r[1]), "=f"(r[2]), "=f"(r[3]),
          "=f"(r[4]), "=f"(r[5]), "=f"(r[6]), "=f"(r[7])
        : "l"(p));
}

// 256-bit global store: 8 floats, ptr must be 32B-aligned.
__device__ __forceinline__ void stg256(float* p, const float r[8]) {
    asm volatile(
        "st.global.L1::evict_first.v8.f32 [%0], {%1,%2,%3,%4,%5,%6,%7,%8};"
        :: "l"(p),
           "f"(r[0]), "f"(r[1]), "f"(r[2]), "f"(r[3]),
           "f"(r[4]), "f"(r[5]), "f"(r[6]), "f"(r[7])
        : "memory");
}

__global__ __launch_bounds__(TPB, 6) void ifo_scan_kernel(
    const float* __restrict__ f,
    const float* __restrict__ z,
    const float* __restrict__ ig,
    float* __restrict__ out)
{
    const int row  = blockIdx.x;
    const int base = row * SEQ;
    const int t    = threadIdx.x;
    const int off  = base + t * EPT;

    // ---- Phase 1: 3 front-batched 256-bit loads ----
    float fv[EPT], zv[EPT], iv[EPT];
    ldg256(f  + off, fv);
    ldg256(z  + off, zv);
    ldg256(ig + off, iv);

    float xv[EPT];
    #pragma unroll
    for (int j = 0; j < EPT; j++) xv[j] = iv[j] * zv[j];

    // local segment composite (F, X): h_out = F*h_in + X
    float F = 1.0f, X = 0.0f;
    #pragma unroll
    for (int j = 0; j < EPT; j++) {
        X = fmaf(fv[j], X, xv[j]);
        F *= fv[j];
    }

    // ---- Phase 2: inclusive warp scan of composites ----
    const unsigned lane = t & 31u;
    const unsigned warp = t >> 5;
    float Fs = F, Xs = X;
    #pragma unroll
    for (int d = 1; d < 32; d <<= 1) {
        float Fo = __shfl_up_sync(0xFFFFFFFFu, Fs, d);
        float Xo = __shfl_up_sync(0xFFFFFFFFu, Xs, d);
        if (lane >= (unsigned)d) {
            Xs = fmaf(Fs, Xo, Xs);   // (Fo,Xo) then (Fs,Xs)
            Fs = Fs * Fo;
        }
    }

    // warp aggregates -> smem (8 warps)
    __shared__ float sF[TPB / 32];
    __shared__ float sX[TPB / 32];
    if (lane == 31) { sF[warp] = Fs; sX[warp] = Xs; }
    __syncthreads();

    // carry from preceding warps (<= 7 fmas)
    float Xc = 0.0f;
    #pragma unroll
    for (int w = 0; w < TPB / 32; w++) {
        if (w < (int)warp) Xc = fmaf(sF[w], Xc, sX[w]);
    }

    // exclusive-within-warp composite = inclusive of lane-1
    float Fex = __shfl_up_sync(0xFFFFFFFFu, Fs, 1);
    float Xex = __shfl_up_sync(0xFFFFFFFFu, Xs, 1);
    if (lane == 0) { Fex = 1.0f; Xex = 0.0f; }

    float h = fmaf(Fex, Xc, Xex);

    // ---- Phase 3: replay from registers, one 256-bit store ----
    float r[EPT];
    #pragma unroll
    for (int j = 0; j < EPT; j++) {
        h = fmaf(fv[j], h, xv[j]);
        r[j] = h;
    }
    stg256(out + off, r);
}

extern "C" void kernel_launch(void* const* d_in, const int* in_sizes, int n_in,
                              void* d_out, int out_size)
{
    const float* f  = (const float*)d_in[0];
    const float* z  = (const float*)d_in[1];
    const float* ig = (const float*)d_in[2];
    float* out = (float*)d_out;

    const int rows = out_size / SEQ;   // 16384
    ifo_scan_kernel<<<rows, TPB>>>(f, z, ig, out);
}